// round 10
// baseline (speedup 1.0000x reference)
#include <cuda_runtime.h>
#include <cuda_bf16.h>
#include <math.h>
#include <mma.h>
#include <stdint.h>

using namespace nvcuda;

// ---------------------------------------------------------------------------
// Problem constants
// ---------------------------------------------------------------------------
#define NN     50000
#define DD     200
#define KK     3
#define R2D    474
#define EE     250000
#define BB     2048
#define HH     100
#define KD     (KK*DD)          // 600
#define NPAIR  3

// ---------------------------------------------------------------------------
// Scratch (static device globals). 16B alignment for float4 / cp.async paths.
// ---------------------------------------------------------------------------
__device__ __align__(16) float g_x[(size_t)NN * KD];
__device__ __align__(16) float g_agg[(size_t)NN * KD];
__device__ __align__(16) float g_xi[(size_t)NPAIR * BB * DD];
__device__ __align__(16) float g_hmu[(size_t)NPAIR * BB * HH];
__device__ __align__(16) float g_hlv[(size_t)NPAIR * BB * HH];
__device__ __align__(16) float g_mu[(size_t)NPAIR * BB * DD];
__device__ __align__(16) float g_lv[(size_t)NPAIR * BB * DD];
// CSR scratch
__device__ int g_deg[NN];
__device__ int g_off[NN + 1];
__device__ int g_cur[NN];
__device__ int g_eord[EE];

// ---------------------------------------------------------------------------
// cp.async helpers
// ---------------------------------------------------------------------------
__device__ __forceinline__ void cp_async16(void* sdst, const void* gsrc, bool pred)
{
    uint32_t s = (uint32_t)__cvta_generic_to_shared(sdst);
    int sz = pred ? 16 : 0;
    asm volatile("cp.async.cg.shared.global [%0], [%1], 16, %2;\n"
                 :: "r"(s), "l"(gsrc), "r"(sz));
}
__device__ __forceinline__ void cp_commit()
{
    asm volatile("cp.async.commit_group;\n");
}
template<int N> __device__ __forceinline__ void cp_wait()
{
    asm volatile("cp.async.wait_group %0;\n" :: "n"(N));
}

// ---------------------------------------------------------------------------
// Zero small scratch (deg + loss)
// ---------------------------------------------------------------------------
__global__ void zero_small_kernel(float* __restrict__ loss_slot)
{
    int i = blockIdx.x * blockDim.x + threadIdx.x;
    if (i < NN) g_deg[i] = 0;
    if (i == 0) *loss_slot = 0.f;
}

// ---------------------------------------------------------------------------
// CSR build: histogram -> scan -> scatter
// ---------------------------------------------------------------------------
__global__ void hist_kernel(const int* __restrict__ ei)
{
    int e = blockIdx.x * blockDim.x + threadIdx.x;
    if (e < EE) atomicAdd(&g_deg[ei[e]], 1);
}

__global__ __launch_bounds__(1024)
void scan_kernel()
{
    __shared__ int part[1024];
    const int t = threadIdx.x;
    const int CH = (NN + 1023) / 1024;
    int s = 0;
#pragma unroll 4
    for (int i = 0; i < CH; i++) {
        int idx = t * CH + i;
        if (idx < NN) s += g_deg[idx];
    }
    part[t] = s;
    __syncthreads();
    int own = s;
    for (int o = 1; o < 1024; o <<= 1) {
        int v = part[t];
        if (t >= o) v += part[t - o];
        __syncthreads();
        part[t] = v;
        __syncthreads();
    }
    int run = part[t] - own;
    for (int i = 0; i < CH; i++) {
        int idx = t * CH + i;
        if (idx < NN) {
            g_off[idx] = run;
            g_cur[idx] = run;
            run += g_deg[idx];
        }
    }
    if (t == 0) g_off[NN] = EE;
}

__global__ void scatter_kernel(const int* __restrict__ ei)
{
    int e = blockIdx.x * blockDim.x + threadIdx.x;
    if (e < EE) {
        int d = ei[e];
        int p = atomicAdd(&g_cur[d], 1);
        g_eord[p] = e;
    }
}

// ---------------------------------------------------------------------------
// Fused attention pass. One warp per (node, k). float4 loads, 2 edges/iter.
// ---------------------------------------------------------------------------
__global__ __launch_bounds__(256)
void node_attn_kernel(const int* __restrict__ ei, const int* __restrict__ etype,
                      const float* __restrict__ r, const float* __restrict__ relw)
{
    int w    = (blockIdx.x * blockDim.x + threadIdx.x) >> 5;
    int lane = threadIdx.x & 31;
    if (w >= NN * KK) return;
    const int node = w / KK;
    const int k    = w - node * KK;

    const float4* xd4 = reinterpret_cast<const float4*>(g_x + (size_t)node * KD + k * DD);
    float4 xd0 = xd4[lane];
    float4 xd1 = (lane < 18) ? xd4[lane + 32] : make_float4(0.f, 0.f, 0.f, 0.f);

    float4 acc0 = make_float4(0.f, 0.f, 0.f, 0.f);
    float4 acc1 = make_float4(0.f, 0.f, 0.f, 0.f);
    float  den  = 0.f;

    const int beg = g_off[node];
    const int end = g_off[node + 1];
    int p = beg;

    for (; p + 1 < end; p += 2) {
        int e0 = g_eord[p];
        int e1 = g_eord[p + 1];
        int src0 = ei[EE + e0], t0 = etype[e0];
        int src1 = ei[EE + e1], t1 = etype[e1];
        float rw0 = relw[t0 * KK + k];
        float rw1 = relw[t1 * KK + k];

        const float4* xsA = reinterpret_cast<const float4*>(g_x + (size_t)src0 * KD + k * DD);
        const float4* rrA = reinterpret_cast<const float4*>(r + (size_t)t0 * DD);
        const float4* xsB = reinterpret_cast<const float4*>(g_x + (size_t)src1 * KD + k * DD);
        const float4* rrB = reinterpret_cast<const float4*>(r + (size_t)t1 * DD);

        float4 aA0 = xsA[lane];
        float4 aB0 = xsB[lane];
        float4 rA0 = rrA[lane];
        float4 rB0 = rrB[lane];
        float4 aA1 = make_float4(0.f,0.f,0.f,0.f), rA1 = aA1;
        float4 aB1 = aA1, rB1 = aA1;
        if (lane < 18) {
            aA1 = xsA[lane + 32];
            aB1 = xsB[lane + 32];
            rA1 = rrA[lane + 32];
            rB1 = rrB[lane + 32];
        }

        float4 mA0 = make_float4(aA0.x*rA0.x, aA0.y*rA0.y, aA0.z*rA0.z, aA0.w*rA0.w);
        float4 mA1 = make_float4(aA1.x*rA1.x, aA1.y*rA1.y, aA1.z*rA1.z, aA1.w*rA1.w);
        float4 mB0 = make_float4(aB0.x*rB0.x, aB0.y*rB0.y, aB0.z*rB0.z, aB0.w*rB0.w);
        float4 mB1 = make_float4(aB1.x*rB1.x, aB1.y*rB1.y, aB1.z*rB1.z, aB1.w*rB1.w);

        float dotA = xd0.x*mA0.x + xd0.y*mA0.y + xd0.z*mA0.z + xd0.w*mA0.w
                   + xd1.x*mA1.x + xd1.y*mA1.y + xd1.z*mA1.z + xd1.w*mA1.w;
        float dotB = xd0.x*mB0.x + xd0.y*mB0.y + xd0.z*mB0.z + xd0.w*mB0.w
                   + xd1.x*mB1.x + xd1.y*mB1.y + xd1.z*mB1.z + xd1.w*mB1.w;
#pragma unroll
        for (int o = 16; o > 0; o >>= 1) {
            dotA += __shfl_xor_sync(0xffffffffu, dotA, o);
            dotB += __shfl_xor_sync(0xffffffffu, dotB, o);
        }

        float lA = dotA * rw0;  lA = (lA > 0.f) ? lA : 0.2f * lA;
        float lB = dotB * rw1;  lB = (lB > 0.f) ? lB : 0.2f * lB;
        float aE0 = __expf(lA);
        float aE1 = __expf(lB);
        den += aE0 + aE1;
        acc0.x += aE0*mA0.x + aE1*mB0.x;  acc0.y += aE0*mA0.y + aE1*mB0.y;
        acc0.z += aE0*mA0.z + aE1*mB0.z;  acc0.w += aE0*mA0.w + aE1*mB0.w;
        acc1.x += aE0*mA1.x + aE1*mB1.x;  acc1.y += aE0*mA1.y + aE1*mB1.y;
        acc1.z += aE0*mA1.z + aE1*mB1.z;  acc1.w += aE0*mA1.w + aE1*mB1.w;
    }

    if (p < end) {
        int e   = g_eord[p];
        int src = ei[EE + e];
        int t   = etype[e];
        float rw = relw[t * KK + k];
        const float4* xs4 = reinterpret_cast<const float4*>(g_x + (size_t)src * KD + k * DD);
        const float4* rr4 = reinterpret_cast<const float4*>(r + (size_t)t * DD);

        float4 a0 = xs4[lane];
        float4 r0 = rr4[lane];
        float4 m0 = make_float4(a0.x*r0.x, a0.y*r0.y, a0.z*r0.z, a0.w*r0.w);
        float4 m1 = make_float4(0.f, 0.f, 0.f, 0.f);
        if (lane < 18) {
            float4 a1 = xs4[lane + 32];
            float4 r1 = rr4[lane + 32];
            m1 = make_float4(a1.x*r1.x, a1.y*r1.y, a1.z*r1.z, a1.w*r1.w);
        }
        float dot = xd0.x*m0.x + xd0.y*m0.y + xd0.z*m0.z + xd0.w*m0.w
                  + xd1.x*m1.x + xd1.y*m1.y + xd1.z*m1.z + xd1.w*m1.w;
#pragma unroll
        for (int o = 16; o > 0; o >>= 1)
            dot += __shfl_xor_sync(0xffffffffu, dot, o);

        float l = dot * rw;
        l = (l > 0.f) ? l : 0.2f * l;
        float a = __expf(l);
        den += a;
        acc0.x += a*m0.x; acc0.y += a*m0.y; acc0.z += a*m0.z; acc0.w += a*m0.w;
        acc1.x += a*m1.x; acc1.y += a*m1.y; acc1.z += a*m1.z; acc1.w += a*m1.w;
    }

    float inv = 1.f / (den + 1e-10f);
    float4* ag4 = reinterpret_cast<float4*>(g_agg + (size_t)node * KD + k * DD);
    ag4[lane] = make_float4(acc0.x * inv, acc0.y * inv, acc0.z * inv, acc0.w * inv);
    if (lane < 18)
        ag4[lane + 32] = make_float4(acc1.x * inv, acc1.y * inv, acc1.z * inv, acc1.w * inv);
}

// ---------------------------------------------------------------------------
// tf32 GEMM core, templated on N-tile TNP and thread count NTH.
// Block tile 128 x TNP; WM=4 warp rows x WN=NTH/128 warp cols;
// every warp owns a 32x32 sub-tile (2x2 fragments) -> low register pressure.
// cp.async double-buffered; C staged through SMEM in 64-col passes.
// act: 0=none 1=tanh 2=relu. bias may be null.
// ---------------------------------------------------------------------------
#define TM 128
#define TKC 16
#define AS_STRIDE (TKC + 4)              // 20
#define AS_SIZE   (TM * AS_STRIDE)       // 2560 floats

template<int TNP> struct SmSize {
    static constexpr int stage = 2 * (AS_SIZE + TKC * (TNP + 4));
    static constexpr int epi   = TM * 64;
    static constexpr int v = (stage > epi) ? stage : epi;
};

template<int TNP, int NTH>
__device__ __forceinline__ void stage_load(
    const float* __restrict__ A, const float* __restrict__ B,
    int M, int N, int Kd, int row0, int col0, int k0,
    float* Asb, float* Bsb)
{
    const int tid = threadIdx.x;
    // A tile: 128 rows x 4 chunks(16B) = 512 chunks
#pragma unroll
    for (int l = 0; l < 512 / NTH; l++) {
        int c = tid + l * NTH;
        int m = c >> 2, q = (c & 3) * 4;
        int gr = row0 + m, gk = k0 + q;
        bool pr = (gr < M) && (gk < Kd);          // Kd % 4 == 0 always
        const float* gp = pr ? (A + (size_t)gr * Kd + gk) : A;
        cp_async16(&Asb[m * AS_STRIDE + q], gp, pr);
    }
    // B tile: TKC rows x TNP/4 chunks = 4*TNP chunks (divisible by NTH)
    constexpr int BCH = TNP / 4;
#pragma unroll
    for (int l = 0; l < (TKC * BCH) / NTH; l++) {
        int idx = tid + l * NTH;
        int kk = idx / BCH;
        int q  = (idx % BCH) * 4;
        int gk = k0 + kk, gc = col0 + q;
        bool pr = (gk < Kd) && (gc < N);          // N % 4 == 0 always
        const float* gp = pr ? (B + (size_t)gk * N + gc) : B;
        cp_async16(&Bsb[kk * (TNP + 4) + q], gp, pr);
    }
    cp_commit();
}

template<int TNP, int NTH>
__device__ __forceinline__ void gemm_core(
    const float* __restrict__ A, const float* __restrict__ B,
    const float* __restrict__ bias, float* __restrict__ C,
    int M, int N, int Kd, int act, float* sm)
{
    constexpr int BSS = TKC * (TNP + 4);
    constexpr int WN  = NTH / 128;       // warps in N dir (2 or 4)
    constexpr int WCOLS = TNP / WN;      // 32 always
    static_assert(WCOLS == 32, "warp tile must be 32 cols");

    float* As0 = sm;
    float* As1 = sm + AS_SIZE;
    float* Bs0 = sm + 2 * AS_SIZE;
    float* Bs1 = Bs0 + BSS;

    const int tid  = threadIdx.x;
    const int warp = tid >> 5;
    const int wm   = warp / WN;          // 0..3
    const int wn   = warp % WN;          // 0..WN-1
    const int row0 = blockIdx.y * TM;
    const int col0 = blockIdx.x * TNP;

    wmma::fragment<wmma::accumulator, 16, 16, 8, float> acc[2][2];
#pragma unroll
    for (int i = 0; i < 2; i++)
#pragma unroll
        for (int j = 0; j < 2; j++)
            wmma::fill_fragment(acc[i][j], 0.0f);

    const int NK = (Kd + TKC - 1) / TKC;
    stage_load<TNP, NTH>(A, B, M, N, Kd, row0, col0, 0, As0, Bs0);

    for (int kt = 0; kt < NK; kt++) {
        float* Asb = (kt & 1) ? As1 : As0;
        float* Bsb = (kt & 1) ? Bs1 : Bs0;
        if (kt + 1 < NK) {
            float* An = ((kt + 1) & 1) ? As1 : As0;
            float* Bn = ((kt + 1) & 1) ? Bs1 : Bs0;
            stage_load<TNP, NTH>(A, B, M, N, Kd, row0, col0, (kt + 1) * TKC, An, Bn);
            cp_wait<1>();
        } else {
            cp_wait<0>();
        }
        __syncthreads();

#pragma unroll
        for (int ks = 0; ks < TKC; ks += 8) {
            wmma::fragment<wmma::matrix_a, 16, 16, 8,
                           wmma::precision::tf32, wmma::row_major> fa[2];
            wmma::fragment<wmma::matrix_b, 16, 16, 8,
                           wmma::precision::tf32, wmma::row_major> fb[2];
#pragma unroll
            for (int i = 0; i < 2; i++) {
                wmma::load_matrix_sync(fa[i], &Asb[(wm * 32 + i * 16) * AS_STRIDE + ks],
                                       AS_STRIDE);
#pragma unroll
                for (int t = 0; t < fa[i].num_elements; t++)
                    fa[i].x[t] = wmma::__float_to_tf32(fa[i].x[t]);
            }
#pragma unroll
            for (int j = 0; j < 2; j++) {
                wmma::load_matrix_sync(fb[j],
                    &Bsb[ks * (TNP + 4) + wn * WCOLS + j * 16], TNP + 4);
#pragma unroll
                for (int t = 0; t < fb[j].num_elements; t++)
                    fb[j].x[t] = wmma::__float_to_tf32(fb[j].x[t]);
            }
#pragma unroll
            for (int i = 0; i < 2; i++)
#pragma unroll
                for (int j = 0; j < 2; j++)
                    wmma::mma_sync(acc[i][j], fa[i], fb[j], acc[i][j]);
        }
        __syncthreads();
    }

    // epilogue: stage C through SMEM in 64-column passes
    float* Cs = sm;
#pragma unroll
    for (int h = 0; h < TNP / 64; h++) {
        int base = h * 64;
#pragma unroll
        for (int i = 0; i < 2; i++)
#pragma unroll
            for (int j = 0; j < 2; j++) {
                int gcol = wn * WCOLS + j * 16;
                if (gcol >= base && gcol < base + 64)
                    wmma::store_matrix_sync(&Cs[(wm * 32 + i * 16) * 64 + (gcol - base)],
                                            acc[i][j], 64, wmma::mem_row_major);
            }
        __syncthreads();
#pragma unroll
        for (int l = 0; l < (TM * 64) / NTH; l++) {
            int idx = tid + l * NTH;
            int m = idx >> 6, n = idx & 63;
            int gr = row0 + m, gc = col0 + base + n;
            if (gr < M && gc < N) {
                float v = Cs[m * 64 + n];
                if (bias) v += bias[gc];
                if (act == 1) v = tanhf(v);
                else if (act == 2) v = fmaxf(v, 0.f);
                C[(size_t)gr * N + gc] = v;
            }
        }
        __syncthreads();
    }
}

template<int TNP, int NTH>
__global__ __launch_bounds__(NTH)
void gemm_tf32_kernel(const float* __restrict__ A, const float* __restrict__ B,
                      const float* __restrict__ bias, float* __restrict__ C,
                      int M, int N, int Kd, int act)
{
    __shared__ float sm[SmSize<TNP>::v];
    gemm_core<TNP, NTH>(A, B, bias, C, M, N, Kd, act, sm);
}

// Batched MI layer-1: z in [0,6): p = z>>1, lv = z&1. relu activation.
__global__ __launch_bounds__(256)
void mi_l1_kernel(const float* __restrict__ mu_w1, const float* __restrict__ mu_b1,
                  const float* __restrict__ lv_w1, const float* __restrict__ lv_b1)
{
    __shared__ float sm[SmSize<64>::v];
    int z = blockIdx.z, p = z >> 1, lv = z & 1;
    const float* A    = g_xi + (size_t)p * BB * DD;
    const float* B    = (lv ? lv_w1 : mu_w1) + (size_t)p * DD * HH;
    const float* bias = (lv ? lv_b1 : mu_b1) + (size_t)p * HH;
    float*       C    = (lv ? g_hlv : g_hmu) + (size_t)p * BB * HH;
    gemm_core<64, 256>(A, B, bias, C, BB, HH, DD, 2, sm);
}

// Batched MI layer-2: mu -> no act, lv -> tanh.
__global__ __launch_bounds__(256)
void mi_l2_kernel(const float* __restrict__ mu_w2, const float* __restrict__ mu_b2,
                  const float* __restrict__ lv_w2, const float* __restrict__ lv_b2)
{
    __shared__ float sm[SmSize<64>::v];
    int z = blockIdx.z, p = z >> 1, lv = z & 1;
    const float* A    = (lv ? g_hlv : g_hmu) + (size_t)p * BB * HH;
    const float* B    = (lv ? lv_w2 : mu_w2) + (size_t)p * HH * DD;
    const float* bias = (lv ? lv_b2 : mu_b2) + (size_t)p * DD;
    float*       C    = (lv ? g_lv : g_mu) + (size_t)p * BB * DD;
    gemm_core<64, 256>(A, B, bias, C, BB, DD, HH, lv ? 1 : 0, sm);
}

// ---------------------------------------------------------------------------
// Gather outputs: sub_emb, rel_emb_single, xi
// ---------------------------------------------------------------------------
__global__ __launch_bounds__(256)
void gather_kernel(const float* __restrict__ xnew, const float* __restrict__ init_rel,
                   const int* __restrict__ sub, const int* __restrict__ rel,
                   float* __restrict__ sub_emb, float* __restrict__ rel_emb)
{
    int b = blockIdx.x;
    int t = threadIdx.x;
    int sb = sub[b];
    const float* srcx = xnew + (size_t)sb * KD;
    float* se = sub_emb + (size_t)b * KD;
    for (int j = t; j < KD; j += 256) se[j] = srcx[j];

    int rb = rel[b];
    const float* srcr = init_rel + (size_t)rb * DD;
    float* re = rel_emb + (size_t)b * DD;
    for (int j = t; j < DD; j += 256) re[j] = srcr[j];

    for (int j = t; j < DD; j += 256) {
        float v0 = srcx[j];           // k = 0
        float v1 = srcx[DD + j];      // k = 1
        g_xi[((size_t)0 * BB + b) * DD + j] = v0;
        g_xi[((size_t)1 * BB + b) * DD + j] = v0;
        g_xi[((size_t)2 * BB + b) * DD + j] = v1;
    }
}

// ---------------------------------------------------------------------------
// MI loss reduction. One warp per (pair, batch element).
// ---------------------------------------------------------------------------
__global__ __launch_bounds__(256)
void mi_loss_kernel(const float* __restrict__ xnew,
                    const int* __restrict__ sub, const int* __restrict__ perm,
                    float* __restrict__ loss_out)
{
    int w    = (blockIdx.x * blockDim.x + threadIdx.x) >> 5;
    int lane = threadIdx.x & 31;
    if (w >= NPAIR * BB) return;
    int p = w / BB;
    int b = w % BB;
    int pj = (p == 0) ? 1 : 2;

    const float* mup = g_mu + ((size_t)p * BB + b) * DD;
    const float* lvp = g_lv + ((size_t)p * BB + b) * DD;
    int sb  = sub[b];
    int sbn = sub[perm[b]];
    const float* yj  = xnew + (size_t)sb  * KD + pj * DD;
    const float* yjn = xnew + (size_t)sbn * KD + pj * DD;

    float s = 0.f;
    for (int d = lane; d < DD; d += 32) {
        float m  = mup[d];
        float iv = expf(-lvp[d]);
        float dp = m - yj[d];
        float dn = m - yjn[d];
        s += (dn * dn - dp * dp) * iv;
    }
#pragma unroll
    for (int o = 16; o > 0; o >>= 1)
        s += __shfl_xor_sync(0xffffffffu, s, o);
    if (lane == 0)
        atomicAdd(loss_out, s / (2.0f * BB));
}

// ---------------------------------------------------------------------------
// Launch
// ---------------------------------------------------------------------------
extern "C" void kernel_launch(void* const* d_in, const int* in_sizes, int n_in,
                              void* d_out, int out_size)
{
    const float *init_embed, *init_rel, *pca_W, *pca_b, *rel_weight, *W_ent;
    const float *mu_w1, *mu_b1, *mu_w2, *mu_b2, *lv_w1, *lv_b1, *lv_w2, *lv_b2;
    const int *edge_index, *edge_type, *sub, *rel, *perm;

    if (in_sizes[0] == 2 * EE) {
        // dict order
        edge_index = (const int*)d_in[0];
        edge_type  = (const int*)d_in[1];
        sub        = (const int*)d_in[2];
        rel        = (const int*)d_in[3];
        perm       = (const int*)d_in[4];
        init_embed = (const float*)d_in[5];
        init_rel   = (const float*)d_in[6];
        pca_W      = (const float*)d_in[7];
        pca_b      = (const float*)d_in[8];
        rel_weight = (const float*)d_in[9];
        W_ent      = (const float*)d_in[10];
        /* d_in[11] = W_rel (dead) */
        mu_w1 = (const float*)d_in[12];
        mu_b1 = (const float*)d_in[13];
        mu_w2 = (const float*)d_in[14];
        mu_b2 = (const float*)d_in[15];
        lv_w1 = (const float*)d_in[16];
        lv_b1 = (const float*)d_in[17];
        lv_w2 = (const float*)d_in[18];
        lv_b2 = (const float*)d_in[19];
    } else {
        // signature order
        init_embed = (const float*)d_in[0];
        init_rel   = (const float*)d_in[1];
        pca_W      = (const float*)d_in[2];
        pca_b      = (const float*)d_in[3];
        rel_weight = (const float*)d_in[4];
        W_ent      = (const float*)d_in[5];
        mu_w1 = (const float*)d_in[7];
        mu_b1 = (const float*)d_in[8];
        mu_w2 = (const float*)d_in[9];
        mu_b2 = (const float*)d_in[10];
        lv_w1 = (const float*)d_in[11];
        lv_b1 = (const float*)d_in[12];
        lv_w2 = (const float*)d_in[13];
        lv_b2 = (const float*)d_in[14];
        edge_index = (const int*)d_in[15];
        edge_type  = (const int*)d_in[16];
        sub        = (const int*)d_in[17];
        rel        = (const int*)d_in[18];
        perm       = (const int*)d_in[19];
    }

    float* out = (float*)d_out;
    const size_t SUB_OFF  = 0;
    const size_t REL_OFF  = (size_t)BB * KD;
    const size_t X_OFF    = REL_OFF + (size_t)BB * DD;
    const size_t LOSS_OFF = X_OFF + (size_t)NN * KD;

    float* sub_emb = out + SUB_OFF;
    float* rel_emb = out + REL_OFF;
    float* xnew    = out + X_OFF;
    float* loss    = out + LOSS_OFF;

    float *p_x, *p_agg;
    cudaGetSymbolAddress((void**)&p_x,   g_x);
    cudaGetSymbolAddress((void**)&p_agg, g_agg);

    // 1. zero deg + loss; start CSR build
    zero_small_kernel<<<(NN + 255) / 256, 256>>>(loss);
    hist_kernel<<<(EE + 255) / 256, 256>>>(edge_index);
    scan_kernel<<<1, 1024>>>();

    // 2. x = tanh(init_embed @ pca_W + pca_b)   (50000 x 600)
    //    128x128 tile / 512 threads: 16 warps, each 32x32 -> low regs/warp
    {
        dim3 g((KD + 127) / 128, (NN + TM - 1) / TM);
        gemm_tf32_kernel<128, 512><<<g, 512>>>(init_embed, pca_W, pca_b, p_x,
                                               NN, KD, DD, 1);
    }

    // 3. finish CSR
    scatter_kernel<<<(EE + 255) / 256, 256>>>(edge_index);

    // 4. fused attention pass, warp per (node,k)
    {
        int blocks = (NN * KK * 32 + 255) / 256;
        node_attn_kernel<<<blocks, 256>>>(edge_index, edge_type,
                                          init_rel, rel_weight);
    }

    // 5. x_new = tanh(agg @ W_ent)  ((N*K) x 200)
    {
        dim3 g((DD + 127) / 128, (NN * KK + TM - 1) / TM);
        gemm_tf32_kernel<128, 512><<<g, 512>>>(p_agg, W_ent, nullptr, xnew,
                                               NN * KK, DD, DD, 1);
    }

    // 6. gathers: sub_emb, rel_emb, xi
    gather_kernel<<<BB, 256>>>(xnew, init_rel, sub, rel, sub_emb, rel_emb);

    // 7. MI head: two batched launches (6 GEMMs each)
    {
        dim3 g1((HH + 63) / 64, (BB + TM - 1) / TM, 6);
        mi_l1_kernel<<<g1, 256>>>(mu_w1, mu_b1, lv_w1, lv_b1);
        dim3 g2((DD + 63) / 64, (BB + TM - 1) / TM, 6);
        mi_l2_kernel<<<g2, 256>>>(mu_w2, mu_b2, lv_w2, lv_b2);
    }

    // 8. MI loss reduction
    {
        int blocks = (NPAIR * BB * 32 + 255) / 256;
        mi_loss_kernel<<<blocks, 256>>>(xnew, sub, perm, loss);
    }

    (void)n_in; (void)out_size;
}

// round 11
// speedup vs baseline: 1.9066x; 1.9066x over previous
#include <cuda_runtime.h>
#include <cuda_bf16.h>
#include <math.h>
#include <mma.h>
#include <stdint.h>

using namespace nvcuda;

// ---------------------------------------------------------------------------
// Problem constants
// ---------------------------------------------------------------------------
#define NN     50000
#define DD     200
#define KK     3
#define R2D    474
#define EE     250000
#define BB     2048
#define HH     100
#define KD     (KK*DD)          // 600
#define NPAIR  3

// ---------------------------------------------------------------------------
// Scratch (static device globals). 16B alignment for float4 / cp.async paths.
// ---------------------------------------------------------------------------
__device__ __align__(16) float g_x[(size_t)NN * KD];
__device__ __align__(16) float g_agg[(size_t)NN * KD];
__device__ __align__(16) float g_xi[(size_t)NPAIR * BB * DD];
__device__ __align__(16) float g_hmu[(size_t)NPAIR * BB * HH];
__device__ __align__(16) float g_hlv[(size_t)NPAIR * BB * HH];
__device__ __align__(16) float g_mu[(size_t)NPAIR * BB * DD];
__device__ __align__(16) float g_lv[(size_t)NPAIR * BB * DD];
// CSR scratch
__device__ int g_deg[NN];
__device__ int g_off[NN + 1];
__device__ int g_cur[NN];
__device__ int g_eord[EE];

// ---------------------------------------------------------------------------
// cp.async helpers
// ---------------------------------------------------------------------------
__device__ __forceinline__ void cp_async16(void* sdst, const void* gsrc, bool pred)
{
    uint32_t s = (uint32_t)__cvta_generic_to_shared(sdst);
    int sz = pred ? 16 : 0;
    asm volatile("cp.async.cg.shared.global [%0], [%1], 16, %2;\n"
                 :: "r"(s), "l"(gsrc), "r"(sz));
}
__device__ __forceinline__ void cp_commit()
{
    asm volatile("cp.async.commit_group;\n");
}
template<int N> __device__ __forceinline__ void cp_wait()
{
    asm volatile("cp.async.wait_group %0;\n" :: "n"(N));
}

// ---------------------------------------------------------------------------
// Zero small scratch (deg + loss)
// ---------------------------------------------------------------------------
__global__ void zero_small_kernel(float* __restrict__ loss_slot)
{
    int i = blockIdx.x * blockDim.x + threadIdx.x;
    if (i < NN) g_deg[i] = 0;
    if (i == 0) *loss_slot = 0.f;
}

// ---------------------------------------------------------------------------
// CSR build: histogram -> scan -> scatter
// ---------------------------------------------------------------------------
__global__ void hist_kernel(const int* __restrict__ ei)
{
    int e = blockIdx.x * blockDim.x + threadIdx.x;
    if (e < EE) atomicAdd(&g_deg[ei[e]], 1);
}

__global__ __launch_bounds__(1024)
void scan_kernel()
{
    __shared__ int part[1024];
    const int t = threadIdx.x;
    const int CH = (NN + 1023) / 1024;
    int s = 0;
#pragma unroll 4
    for (int i = 0; i < CH; i++) {
        int idx = t * CH + i;
        if (idx < NN) s += g_deg[idx];
    }
    part[t] = s;
    __syncthreads();
    int own = s;
    for (int o = 1; o < 1024; o <<= 1) {
        int v = part[t];
        if (t >= o) v += part[t - o];
        __syncthreads();
        part[t] = v;
        __syncthreads();
    }
    int run = part[t] - own;
    for (int i = 0; i < CH; i++) {
        int idx = t * CH + i;
        if (idx < NN) {
            g_off[idx] = run;
            g_cur[idx] = run;
            run += g_deg[idx];
        }
    }
    if (t == 0) g_off[NN] = EE;
}

__global__ void scatter_kernel(const int* __restrict__ ei)
{
    int e = blockIdx.x * blockDim.x + threadIdx.x;
    if (e < EE) {
        int d = ei[e];
        int p = atomicAdd(&g_cur[d], 1);
        g_eord[p] = e;
    }
}

// ---------------------------------------------------------------------------
// Fused attention pass. One warp per (node, k). float4 loads, 2 edges/iter.
// ---------------------------------------------------------------------------
__global__ __launch_bounds__(256)
void node_attn_kernel(const int* __restrict__ ei, const int* __restrict__ etype,
                      const float* __restrict__ r, const float* __restrict__ relw)
{
    int w    = (blockIdx.x * blockDim.x + threadIdx.x) >> 5;
    int lane = threadIdx.x & 31;
    if (w >= NN * KK) return;
    const int node = w / KK;
    const int k    = w - node * KK;

    const float4* xd4 = reinterpret_cast<const float4*>(g_x + (size_t)node * KD + k * DD);
    float4 xd0 = xd4[lane];
    float4 xd1 = (lane < 18) ? xd4[lane + 32] : make_float4(0.f, 0.f, 0.f, 0.f);

    float4 acc0 = make_float4(0.f, 0.f, 0.f, 0.f);
    float4 acc1 = make_float4(0.f, 0.f, 0.f, 0.f);
    float  den  = 0.f;

    const int beg = g_off[node];
    const int end = g_off[node + 1];
    int p = beg;

    for (; p + 1 < end; p += 2) {
        int e0 = g_eord[p];
        int e1 = g_eord[p + 1];
        int src0 = ei[EE + e0], t0 = etype[e0];
        int src1 = ei[EE + e1], t1 = etype[e1];
        float rw0 = relw[t0 * KK + k];
        float rw1 = relw[t1 * KK + k];

        const float4* xsA = reinterpret_cast<const float4*>(g_x + (size_t)src0 * KD + k * DD);
        const float4* rrA = reinterpret_cast<const float4*>(r + (size_t)t0 * DD);
        const float4* xsB = reinterpret_cast<const float4*>(g_x + (size_t)src1 * KD + k * DD);
        const float4* rrB = reinterpret_cast<const float4*>(r + (size_t)t1 * DD);

        float4 aA0 = xsA[lane];
        float4 aB0 = xsB[lane];
        float4 rA0 = rrA[lane];
        float4 rB0 = rrB[lane];
        float4 aA1 = make_float4(0.f,0.f,0.f,0.f), rA1 = aA1;
        float4 aB1 = aA1, rB1 = aA1;
        if (lane < 18) {
            aA1 = xsA[lane + 32];
            aB1 = xsB[lane + 32];
            rA1 = rrA[lane + 32];
            rB1 = rrB[lane + 32];
        }

        float4 mA0 = make_float4(aA0.x*rA0.x, aA0.y*rA0.y, aA0.z*rA0.z, aA0.w*rA0.w);
        float4 mA1 = make_float4(aA1.x*rA1.x, aA1.y*rA1.y, aA1.z*rA1.z, aA1.w*rA1.w);
        float4 mB0 = make_float4(aB0.x*rB0.x, aB0.y*rB0.y, aB0.z*rB0.z, aB0.w*rB0.w);
        float4 mB1 = make_float4(aB1.x*rB1.x, aB1.y*rB1.y, aB1.z*rB1.z, aB1.w*rB1.w);

        float dotA = xd0.x*mA0.x + xd0.y*mA0.y + xd0.z*mA0.z + xd0.w*mA0.w
                   + xd1.x*mA1.x + xd1.y*mA1.y + xd1.z*mA1.z + xd1.w*mA1.w;
        float dotB = xd0.x*mB0.x + xd0.y*mB0.y + xd0.z*mB0.z + xd0.w*mB0.w
                   + xd1.x*mB1.x + xd1.y*mB1.y + xd1.z*mB1.z + xd1.w*mB1.w;
#pragma unroll
        for (int o = 16; o > 0; o >>= 1) {
            dotA += __shfl_xor_sync(0xffffffffu, dotA, o);
            dotB += __shfl_xor_sync(0xffffffffu, dotB, o);
        }

        float lA = dotA * rw0;  lA = (lA > 0.f) ? lA : 0.2f * lA;
        float lB = dotB * rw1;  lB = (lB > 0.f) ? lB : 0.2f * lB;
        float aE0 = __expf(lA);
        float aE1 = __expf(lB);
        den += aE0 + aE1;
        acc0.x += aE0*mA0.x + aE1*mB0.x;  acc0.y += aE0*mA0.y + aE1*mB0.y;
        acc0.z += aE0*mA0.z + aE1*mB0.z;  acc0.w += aE0*mA0.w + aE1*mB0.w;
        acc1.x += aE0*mA1.x + aE1*mB1.x;  acc1.y += aE0*mA1.y + aE1*mB1.y;
        acc1.z += aE0*mA1.z + aE1*mB1.z;  acc1.w += aE0*mA1.w + aE1*mB1.w;
    }

    if (p < end) {
        int e   = g_eord[p];
        int src = ei[EE + e];
        int t   = etype[e];
        float rw = relw[t * KK + k];
        const float4* xs4 = reinterpret_cast<const float4*>(g_x + (size_t)src * KD + k * DD);
        const float4* rr4 = reinterpret_cast<const float4*>(r + (size_t)t * DD);

        float4 a0 = xs4[lane];
        float4 r0 = rr4[lane];
        float4 m0 = make_float4(a0.x*r0.x, a0.y*r0.y, a0.z*r0.z, a0.w*r0.w);
        float4 m1 = make_float4(0.f, 0.f, 0.f, 0.f);
        if (lane < 18) {
            float4 a1 = xs4[lane + 32];
            float4 r1 = rr4[lane + 32];
            m1 = make_float4(a1.x*r1.x, a1.y*r1.y, a1.z*r1.z, a1.w*r1.w);
        }
        float dot = xd0.x*m0.x + xd0.y*m0.y + xd0.z*m0.z + xd0.w*m0.w
                  + xd1.x*m1.x + xd1.y*m1.y + xd1.z*m1.z + xd1.w*m1.w;
#pragma unroll
        for (int o = 16; o > 0; o >>= 1)
            dot += __shfl_xor_sync(0xffffffffu, dot, o);

        float l = dot * rw;
        l = (l > 0.f) ? l : 0.2f * l;
        float a = __expf(l);
        den += a;
        acc0.x += a*m0.x; acc0.y += a*m0.y; acc0.z += a*m0.z; acc0.w += a*m0.w;
        acc1.x += a*m1.x; acc1.y += a*m1.y; acc1.z += a*m1.z; acc1.w += a*m1.w;
    }

    float inv = 1.f / (den + 1e-10f);
    float4* ag4 = reinterpret_cast<float4*>(g_agg + (size_t)node * KD + k * DD);
    ag4[lane] = make_float4(acc0.x * inv, acc0.y * inv, acc0.z * inv, acc0.w * inv);
    if (lane < 18)
        ag4[lane + 32] = make_float4(acc1.x * inv, acc1.y * inv, acc1.z * inv, acc1.w * inv);
}

// ---------------------------------------------------------------------------
// tf32 GEMM core: 128x64 block tile, 8 warps (4x2), warp tile 32x32.
// 3-stage cp.async pipeline; SMEM reused for the C epilogue tile.
// act: 0=none 1=tanh 2=relu. bias may be null.
// ---------------------------------------------------------------------------
#define TM 128
#define TN 64
#define TKC 16
#define AS_STRIDE (TKC + 4)              // 20
#define BS_STRIDE (TN + 4)               // 68
#define AS_SIZE   (TM * AS_STRIDE)       // 2560 floats
#define BS_SIZE   (TKC * BS_STRIDE)      // 1088 floats
#define STAGE_SZ  (AS_SIZE + BS_SIZE)    // 3648 floats
#define SM_FLOATS (3 * STAGE_SZ)         // 10944 floats = 43.8KB (>= epi 8192)

__device__ __forceinline__ void stage_load(
    const float* __restrict__ A, const float* __restrict__ B,
    int M, int N, int Kd, int row0, int col0, int k0,
    float* Asb, float* Bsb)
{
    const int tid = threadIdx.x;
    // A tile: 128 rows x 4 chunks(16B) = 512 chunks, 2 per thread
#pragma unroll
    for (int l = 0; l < 2; l++) {
        int c = tid + l * 256;
        int m = c >> 2, q = (c & 3) * 4;
        int gr = row0 + m, gk = k0 + q;
        bool pr = (gr < M) && (gk < Kd);          // Kd % 4 == 0 always
        const float* gp = pr ? (A + (size_t)gr * Kd + gk) : A;
        cp_async16(&Asb[m * AS_STRIDE + q], gp, pr);
    }
    // B tile: 16 rows x 16 chunks = 256 chunks, 1 per thread
    {
        int kk = tid >> 4, q = (tid & 15) * 4;
        int gk = k0 + kk, gc = col0 + q;
        bool pr = (gk < Kd) && (gc < N);          // N % 4 == 0 always
        const float* gp = pr ? (B + (size_t)gk * N + gc) : B;
        cp_async16(&Bsb[kk * BS_STRIDE + q], gp, pr);
    }
    cp_commit();
}

__device__ __forceinline__ void gemm_core(
    const float* __restrict__ A, const float* __restrict__ B,
    const float* __restrict__ bias, float* __restrict__ C,
    int M, int N, int Kd, int act, float* sm)
{
    const int tid  = threadIdx.x;
    const int warp = tid >> 5;
    const int wm   = warp >> 1;
    const int wn   = warp & 1;
    const int row0 = blockIdx.y * TM;
    const int col0 = blockIdx.x * TN;

    wmma::fragment<wmma::accumulator, 16, 16, 8, float> acc[2][2];
#pragma unroll
    for (int i = 0; i < 2; i++)
#pragma unroll
        for (int j = 0; j < 2; j++)
            wmma::fill_fragment(acc[i][j], 0.0f);

    const int NK = (Kd + TKC - 1) / TKC;

    // prologue: fill stages 0 and 1
    stage_load(A, B, M, N, Kd, row0, col0, 0,
               sm, sm + AS_SIZE);
    if (NK > 1)
        stage_load(A, B, M, N, Kd, row0, col0, TKC,
                   sm + STAGE_SZ, sm + STAGE_SZ + AS_SIZE);

    for (int kt = 0; kt < NK; kt++) {
        // issue stage kt+2, then wait for stage kt
        if (kt + 2 < NK) {
            float* base = sm + ((kt + 2) % 3) * STAGE_SZ;
            stage_load(A, B, M, N, Kd, row0, col0, (kt + 2) * TKC,
                       base, base + AS_SIZE);
            cp_wait<2>();
        } else if (kt + 1 < NK) {
            cp_wait<1>();
        } else {
            cp_wait<0>();
        }
        __syncthreads();

        float* Asb = sm + (kt % 3) * STAGE_SZ;
        float* Bsb = Asb + AS_SIZE;

#pragma unroll
        for (int ks = 0; ks < TKC; ks += 8) {
            wmma::fragment<wmma::matrix_a, 16, 16, 8,
                           wmma::precision::tf32, wmma::row_major> fa[2];
            wmma::fragment<wmma::matrix_b, 16, 16, 8,
                           wmma::precision::tf32, wmma::row_major> fb[2];
#pragma unroll
            for (int i = 0; i < 2; i++) {
                wmma::load_matrix_sync(fa[i], &Asb[(wm * 32 + i * 16) * AS_STRIDE + ks],
                                       AS_STRIDE);
#pragma unroll
                for (int t = 0; t < fa[i].num_elements; t++)
                    fa[i].x[t] = wmma::__float_to_tf32(fa[i].x[t]);
            }
#pragma unroll
            for (int j = 0; j < 2; j++) {
                wmma::load_matrix_sync(fb[j], &Bsb[ks * BS_STRIDE + wn * 32 + j * 16],
                                       BS_STRIDE);
#pragma unroll
                for (int t = 0; t < fb[j].num_elements; t++)
                    fb[j].x[t] = wmma::__float_to_tf32(fb[j].x[t]);
            }
#pragma unroll
            for (int i = 0; i < 2; i++)
#pragma unroll
                for (int j = 0; j < 2; j++)
                    wmma::mma_sync(acc[i][j], fa[i], fb[j], acc[i][j]);
        }
        __syncthreads();
    }

    // epilogue: reuse smem as C tile (128 x 64)
    float* Cs = sm;
#pragma unroll
    for (int i = 0; i < 2; i++)
#pragma unroll
        for (int j = 0; j < 2; j++)
            wmma::store_matrix_sync(&Cs[(wm * 32 + i * 16) * TN + wn * 32 + j * 16],
                                    acc[i][j], TN, wmma::mem_row_major);
    __syncthreads();

#pragma unroll
    for (int l = 0; l < (TM * TN) / 256; l++) {
        int idx = tid + l * 256;
        int m = idx / TN;
        int n = idx % TN;
        int gr = row0 + m, gc = col0 + n;
        if (gr < M && gc < N) {
            float v = Cs[m * TN + n];
            if (bias) v += bias[gc];
            if (act == 1) v = tanhf(v);
            else if (act == 2) v = fmaxf(v, 0.f);
            C[(size_t)gr * N + gc] = v;
        }
    }
}

__global__ __launch_bounds__(256)
void gemm_tf32_kernel(const float* __restrict__ A, const float* __restrict__ B,
                      const float* __restrict__ bias, float* __restrict__ C,
                      int M, int N, int Kd, int act)
{
    __shared__ float sm[SM_FLOATS];
    gemm_core(A, B, bias, C, M, N, Kd, act, sm);
}

// Batched MI layer-1: z in [0,6): p = z>>1, lv = z&1. relu activation.
__global__ __launch_bounds__(256)
void mi_l1_kernel(const float* __restrict__ mu_w1, const float* __restrict__ mu_b1,
                  const float* __restrict__ lv_w1, const float* __restrict__ lv_b1)
{
    __shared__ float sm[SM_FLOATS];
    int z = blockIdx.z, p = z >> 1, lv = z & 1;
    const float* A    = g_xi + (size_t)p * BB * DD;
    const float* B    = (lv ? lv_w1 : mu_w1) + (size_t)p * DD * HH;
    const float* bias = (lv ? lv_b1 : mu_b1) + (size_t)p * HH;
    float*       C    = (lv ? g_hlv : g_hmu) + (size_t)p * BB * HH;
    gemm_core(A, B, bias, C, BB, HH, DD, 2, sm);
}

// Batched MI layer-2: mu -> no act, lv -> tanh.
__global__ __launch_bounds__(256)
void mi_l2_kernel(const float* __restrict__ mu_w2, const float* __restrict__ mu_b2,
                  const float* __restrict__ lv_w2, const float* __restrict__ lv_b2)
{
    __shared__ float sm[SM_FLOATS];
    int z = blockIdx.z, p = z >> 1, lv = z & 1;
    const float* A    = (lv ? g_hlv : g_hmu) + (size_t)p * BB * HH;
    const float* B    = (lv ? lv_w2 : mu_w2) + (size_t)p * HH * DD;
    const float* bias = (lv ? lv_b2 : mu_b2) + (size_t)p * DD;
    float*       C    = (lv ? g_lv : g_mu) + (size_t)p * BB * DD;
    gemm_core(A, B, bias, C, BB, DD, HH, lv ? 1 : 0, sm);
}

// ---------------------------------------------------------------------------
// Gather outputs: sub_emb, rel_emb_single, xi
// ---------------------------------------------------------------------------
__global__ __launch_bounds__(256)
void gather_kernel(const float* __restrict__ xnew, const float* __restrict__ init_rel,
                   const int* __restrict__ sub, const int* __restrict__ rel,
                   float* __restrict__ sub_emb, float* __restrict__ rel_emb)
{
    int b = blockIdx.x;
    int t = threadIdx.x;
    int sb = sub[b];
    const float* srcx = xnew + (size_t)sb * KD;
    float* se = sub_emb + (size_t)b * KD;
    for (int j = t; j < KD; j += 256) se[j] = srcx[j];

    int rb = rel[b];
    const float* srcr = init_rel + (size_t)rb * DD;
    float* re = rel_emb + (size_t)b * DD;
    for (int j = t; j < DD; j += 256) re[j] = srcr[j];

    for (int j = t; j < DD; j += 256) {
        float v0 = srcx[j];           // k = 0
        float v1 = srcx[DD + j];      // k = 1
        g_xi[((size_t)0 * BB + b) * DD + j] = v0;
        g_xi[((size_t)1 * BB + b) * DD + j] = v0;
        g_xi[((size_t)2 * BB + b) * DD + j] = v1;
    }
}

// ---------------------------------------------------------------------------
// MI loss reduction. One warp per (pair, batch element).
// ---------------------------------------------------------------------------
__global__ __launch_bounds__(256)
void mi_loss_kernel(const float* __restrict__ xnew,
                    const int* __restrict__ sub, const int* __restrict__ perm,
                    float* __restrict__ loss_out)
{
    int w    = (blockIdx.x * blockDim.x + threadIdx.x) >> 5;
    int lane = threadIdx.x & 31;
    if (w >= NPAIR * BB) return;
    int p = w / BB;
    int b = w % BB;
    int pj = (p == 0) ? 1 : 2;

    const float* mup = g_mu + ((size_t)p * BB + b) * DD;
    const float* lvp = g_lv + ((size_t)p * BB + b) * DD;
    int sb  = sub[b];
    int sbn = sub[perm[b]];
    const float* yj  = xnew + (size_t)sb  * KD + pj * DD;
    const float* yjn = xnew + (size_t)sbn * KD + pj * DD;

    float s = 0.f;
    for (int d = lane; d < DD; d += 32) {
        float m  = mup[d];
        float iv = expf(-lvp[d]);
        float dp = m - yj[d];
        float dn = m - yjn[d];
        s += (dn * dn - dp * dp) * iv;
    }
#pragma unroll
    for (int o = 16; o > 0; o >>= 1)
        s += __shfl_xor_sync(0xffffffffu, s, o);
    if (lane == 0)
        atomicAdd(loss_out, s / (2.0f * BB));
}

// ---------------------------------------------------------------------------
// Launch
// ---------------------------------------------------------------------------
extern "C" void kernel_launch(void* const* d_in, const int* in_sizes, int n_in,
                              void* d_out, int out_size)
{
    const float *init_embed, *init_rel, *pca_W, *pca_b, *rel_weight, *W_ent;
    const float *mu_w1, *mu_b1, *mu_w2, *mu_b2, *lv_w1, *lv_b1, *lv_w2, *lv_b2;
    const int *edge_index, *edge_type, *sub, *rel, *perm;

    if (in_sizes[0] == 2 * EE) {
        // dict order
        edge_index = (const int*)d_in[0];
        edge_type  = (const int*)d_in[1];
        sub        = (const int*)d_in[2];
        rel        = (const int*)d_in[3];
        perm       = (const int*)d_in[4];
        init_embed = (const float*)d_in[5];
        init_rel   = (const float*)d_in[6];
        pca_W      = (const float*)d_in[7];
        pca_b      = (const float*)d_in[8];
        rel_weight = (const float*)d_in[9];
        W_ent      = (const float*)d_in[10];
        /* d_in[11] = W_rel (dead) */
        mu_w1 = (const float*)d_in[12];
        mu_b1 = (const float*)d_in[13];
        mu_w2 = (const float*)d_in[14];
        mu_b2 = (const float*)d_in[15];
        lv_w1 = (const float*)d_in[16];
        lv_b1 = (const float*)d_in[17];
        lv_w2 = (const float*)d_in[18];
        lv_b2 = (const float*)d_in[19];
    } else {
        // signature order
        init_embed = (const float*)d_in[0];
        init_rel   = (const float*)d_in[1];
        pca_W      = (const float*)d_in[2];
        pca_b      = (const float*)d_in[3];
        rel_weight = (const float*)d_in[4];
        W_ent      = (const float*)d_in[5];
        mu_w1 = (const float*)d_in[7];
        mu_b1 = (const float*)d_in[8];
        mu_w2 = (const float*)d_in[9];
        mu_b2 = (const float*)d_in[10];
        lv_w1 = (const float*)d_in[11];
        lv_b1 = (const float*)d_in[12];
        lv_w2 = (const float*)d_in[13];
        lv_b2 = (const float*)d_in[14];
        edge_index = (const int*)d_in[15];
        edge_type  = (const int*)d_in[16];
        sub        = (const int*)d_in[17];
        rel        = (const int*)d_in[18];
        perm       = (const int*)d_in[19];
    }

    float* out = (float*)d_out;
    const size_t SUB_OFF  = 0;
    const size_t REL_OFF  = (size_t)BB * KD;
    const size_t X_OFF    = REL_OFF + (size_t)BB * DD;
    const size_t LOSS_OFF = X_OFF + (size_t)NN * KD;

    float* sub_emb = out + SUB_OFF;
    float* rel_emb = out + REL_OFF;
    float* xnew    = out + X_OFF;
    float* loss    = out + LOSS_OFF;

    float *p_x, *p_agg;
    cudaGetSymbolAddress((void**)&p_x,   g_x);
    cudaGetSymbolAddress((void**)&p_agg, g_agg);

    // 1. zero deg + loss; start CSR build
    zero_small_kernel<<<(NN + 255) / 256, 256>>>(loss);
    hist_kernel<<<(EE + 255) / 256, 256>>>(edge_index);
    scan_kernel<<<1, 1024>>>();

    // 2. x = tanh(init_embed @ pca_W + pca_b)   (50000 x 600)
    //    (launch slot #4 -> gets profiled by the ncu window)
    {
        dim3 g((KD + TN - 1) / TN, (NN + TM - 1) / TM);
        gemm_tf32_kernel<<<g, 256>>>(init_embed, pca_W, pca_b, p_x,
                                     NN, KD, DD, 1);
    }

    // 3. finish CSR
    scatter_kernel<<<(EE + 255) / 256, 256>>>(edge_index);

    // 4. fused attention pass, warp per (node,k)
    {
        int blocks = (NN * KK * 32 + 255) / 256;
        node_attn_kernel<<<blocks, 256>>>(edge_index, edge_type,
                                          init_rel, rel_weight);
    }

    // 5. x_new = tanh(agg @ W_ent)  ((N*K) x 200)
    {
        dim3 g((DD + TN - 1) / TN, (NN * KK + TM - 1) / TM);
        gemm_tf32_kernel<<<g, 256>>>(p_agg, W_ent, nullptr, xnew,
                                     NN * KK, DD, DD, 1);
    }

    // 6. gathers: sub_emb, rel_emb, xi
    gather_kernel<<<BB, 256>>>(xnew, init_rel, sub, rel, sub_emb, rel_emb);

    // 7. MI head: two batched launches (6 GEMMs each)
    {
        dim3 g1((HH + TN - 1) / TN, (BB + TM - 1) / TM, 6);
        mi_l1_kernel<<<g1, 256>>>(mu_w1, mu_b1, lv_w1, lv_b1);
        dim3 g2((DD + TN - 1) / TN, (BB + TM - 1) / TM, 6);
        mi_l2_kernel<<<g2, 256>>>(mu_w2, mu_b2, lv_w2, lv_b2);
    }

    // 8. MI loss reduction
    {
        int blocks = (NPAIR * BB * 32 + 255) / 256;
        mi_loss_kernel<<<blocks, 256>>>(xnew, sub, perm, loss);
    }

    (void)n_in; (void)out_size;
}